// round 13
// baseline (speedup 1.0000x reference)
#include <cuda_runtime.h>
#include <cuda_fp16.h>
#include <cstdint>

// CostVolume: cost[b,i,h,x] = (1/128) sum_c L[b,c,h,x]*R[b,c,h,x-i], 0 for x<i.
// b=8 c=128 h=96 w=320, 48 disp, fp32.
// v13: warp-specialized producer/consumer on v8's proven fp16 mma path.
//   consumers (warps 0-3): A convert + all mma (warp = m-tile x 8 n-tiles, C[8][4])
//   producers (warps 4-7): B stream (LDG->cvt->STS), free-running across all 4
//     k-slices (disjoint tile columns -> no back-pressure barrier), bar.arrive
//     on named barrier FULL[kc]; consumers bar.sync. 1 barrier/slice, as v8.
//   producer STS lane map (kp in lane>>3, n-octet lane&7) is bank-conflict-free.

#define BB 8
#define CH 128
#define HH 96
#define WW 320
#define MAXD 48
#define PLANE (HH*WW)

#define ROWB 256         // fp16 tile row bytes: 128 k * 2B
#define AF 0             // A fp16: 64*256  = 16384
#define BF 16384         // B fp16: 112*256 = 28672
#define SMEM_TOTAL 45056

__device__ __forceinline__ uint32_t gfun(uint32_t m){
    return ((((m>>2)&1)<<2) | ((((m>>1)^(m>>4))&1)<<1) | (((m^(m>>3))&1)));
}
__device__ __forceinline__ uint32_t smem_u32(const void* p){
    uint32_t a;
    asm("{ .reg .u64 t; cvta.to.shared.u64 t, %1; cvt.u32.u64 %0, t; }" : "=r"(a) : "l"(p));
    return a;
}
__device__ __forceinline__ uint32_t cvt_f16x2(float v0, float v1){
    uint32_t r;
    asm("cvt.rn.f16x2.f32 %0, %1, %2;" : "=r"(r) : "f"(v1), "f"(v0));
    return r;
}
__device__ __forceinline__ void ldsm_x4(uint32_t* r, uint32_t addr){
    asm volatile("ldmatrix.sync.aligned.m8n8.x4.shared.b16 {%0,%1,%2,%3}, [%4];"
                 : "=r"(r[0]), "=r"(r[1]), "=r"(r[2]), "=r"(r[3]) : "r"(addr));
}
__device__ __forceinline__ void mma16816(float* c, const uint32_t* a, const uint32_t* b){
    asm volatile("mma.sync.aligned.m16n8k16.row.col.f32.f16.f16.f32 "
                 "{%0,%1,%2,%3}, {%4,%5,%6,%7}, {%8,%9}, {%0,%1,%2,%3};"
                 : "+f"(c[0]), "+f"(c[1]), "+f"(c[2]), "+f"(c[3])
                 : "r"(a[0]), "r"(a[1]), "r"(a[2]), "r"(a[3]), "r"(b[0]), "r"(b[1]));
}
__device__ __forceinline__ float4 zero4(){ return make_float4(0.f,0.f,0.f,0.f); }

#define BAR_SYNC(id, cnt)   asm volatile("bar.sync %0, %1;"   :: "r"(id), "r"(cnt) : "memory")
#define BAR_ARRIVE(id, cnt) asm volatile("bar.arrive %0, %1;" :: "r"(id), "r"(cnt) : "memory")

__global__ __launch_bounds__(256, 3)
void costvol_v13_kernel(const float* __restrict__ L,
                        const float* __restrict__ R,
                        float* __restrict__ out)
{
    extern __shared__ char smem[];
    const uint32_t sb = smem_u32(smem);

    const int tid  = threadIdx.x;
    const int warp = tid >> 5;
    const int lane = tid & 31;

    const int xt = blockIdx.x % 5;
    const int bh = blockIdx.x / 5;
    const int h  = bh % HH;
    const int b  = bh / HH;
    const int X0 = 64 * xt;

    const float* Lbh = L + ((size_t)b * CH * HH + h) * WW;
    const float* Rbh = R + ((size_t)b * CH * HH + h) * WW;

    float* Ob = (float*)smem;            // epilogue buffer overlays A tile

    if (warp < 4){
        // ======================= CONSUMER (warps 0-3) =======================
        // A convert: 2 tasks/thread: kp = kplA, kplA+8; m4 = tid&15
        const int kplA = tid >> 4;       // 0..7
        const int m4a  = tid & 15;
        const float* pLa = Lbh + X0 + 4 * m4a;
        uint32_t gA[4];
        #pragma unroll
        for (int e = 0; e < 4; e++) gA[e] = gfun((uint32_t)(4*m4a + e));

        // mma constants: warp = m-tile mt, n-tiles 2mt..2mt+7
        const int mt = warp;
        const int m0 = 16 * mt;
        const int lg = lane >> 3, l8 = lane & 7;
        const int arow = m0 + l8 + ((lg & 1) ? 8 : 0);
        const int asel = lg >> 1;
        const uint32_t gAr = gfun((uint32_t)arow);
        const int colselB = (lane >> 3) & 1;
        const int hi16 = (lane >> 4) & 1;
        int brow[4]; uint32_t gB4[4];
        #pragma unroll
        for (int j = 0; j < 4; j++){
            brow[j] = 8 * (2*mt + 2*j + hi16) + (lane & 7);
            gB4[j]  = gfun((uint32_t)brow[j]);
        }

        float C[8][4];
        #pragma unroll
        for (int t = 0; t < 8; t++)
            #pragma unroll
            for (int f = 0; f < 4; f++) C[t][f] = 0.f;

        float4 a0, a1, a2, a3;
        auto loadA = [&](int kc){
            int c0 = 2 * (kc * 16 + kplA);
            a0 = *(const float4*)(pLa + (size_t)c0 * PLANE);
            a1 = *(const float4*)(pLa + (size_t)(c0 + 1) * PLANE);
            int c1 = 2 * (kc * 16 + kplA + 8);
            a2 = *(const float4*)(pLa + (size_t)c1 * PLANE);
            a3 = *(const float4*)(pLa + (size_t)(c1 + 1) * PLANE);
        };
        auto cvtA = [&](int kc){
            {   uint32_t kpg = (uint32_t)(kc * 16 + kplA);
                uint32_t c16 = kpg >> 2, w4 = (kpg & 3) << 2;
                const float va[4] = {a0.x, a0.y, a0.z, a0.w};
                const float vb[4] = {a1.x, a1.y, a1.z, a1.w};
                #pragma unroll
                for (int e = 0; e < 4; e++){
                    uint32_t m = (uint32_t)(4*m4a + e);
                    uint32_t off = m * ROWB + ((c16 ^ gA[e]) << 4) + w4;
                    *(uint32_t*)(smem + AF + off) = cvt_f16x2(va[e], vb[e]);
                }
            }
            {   uint32_t kpg = (uint32_t)(kc * 16 + kplA + 8);
                uint32_t c16 = kpg >> 2, w4 = (kpg & 3) << 2;
                const float va[4] = {a2.x, a2.y, a2.z, a2.w};
                const float vb[4] = {a3.x, a3.y, a3.z, a3.w};
                #pragma unroll
                for (int e = 0; e < 4; e++){
                    uint32_t m = (uint32_t)(4*m4a + e);
                    uint32_t off = m * ROWB + ((c16 ^ gA[e]) << 4) + w4;
                    *(uint32_t*)(smem + AF + off) = cvt_f16x2(va[e], vb[e]);
                }
            }
        };

        loadA(0);
        #pragma unroll 1
        for (int kc = 0; kc < 4; kc++){
            cvtA(kc);
            if (kc < 3) loadA(kc + 1);
            BAR_SYNC(kc + 1, 256);       // A (consumers) + B (producers) ready

            #pragma unroll
            for (int ktl = 0; ktl < 2; ktl++){
                uint32_t colA = (uint32_t)(kc * 4 + 2 * ktl + asel);
                uint32_t af[4];
                ldsm_x4(af, sb + AF + (uint32_t)arow * ROWB + ((colA ^ gAr) << 4));
                #pragma unroll
                for (int j = 0; j < 4; j++){
                    uint32_t colB = (uint32_t)(kc * 4 + 2 * ktl + colselB);
                    uint32_t bf[4];
                    ldsm_x4(bf, sb + BF + (uint32_t)brow[j] * ROWB + ((colB ^ gB4[j]) << 4));
                    mma16816(C[2*j],     af, bf);       // n-tile 2mt+2j
                    mma16816(C[2*j + 1], af, bf + 2);   // n-tile 2mt+2j+1
                }
            }
        }
        BAR_SYNC(5, 128);                // consumers all done before Ob overlays A

        // band extract into Ob[i][m] (stride 68), scale 1/128
        const int r  = lane >> 2;
        const int cb = 2 * (lane & 3);
        const float scale = 1.0f / 128.0f;
        #pragma unroll
        for (int tn = 0; tn < 8; tn++){
            int p = 2*mt + tn;
            #pragma unroll
            for (int f = 0; f < 4; f++){
                int row  = r + ((f >= 2) ? 8 : 0);
                int col  = cb + (f & 1);
                int mloc = m0 + row;
                int n    = 8*p + col;
                int i    = mloc + 48 - n;
                if (i >= 0 && i < MAXD)
                    Ob[i * 68 + mloc] = C[tn][f] * scale;
            }
        }
    } else {
        // ======================= PRODUCER (warps 4-7) =======================
        // thread -> fixed kp = 4*pw + kpq; mini-task s: (kc = s>>2, g4 = s&3)
        // covers n4 = 8*g4 + n8 (valid n4 < 28). STS is bank-conflict-free.
        const int pw  = warp - 4;            // 0..3
        const int kpq = (lane >> 3) & 3;     // 0..3 -> kpg&3 (word-in-16B)
        const int n8  = lane & 7;
        const int kp  = 4 * pw + kpq;        // 0..15
        const uint32_t w4 = (uint32_t)kpq << 2;

        float4 ba[3], bb[3];
        auto ldB = [&](int s){
            int kc = s >> 2, g4 = s & 3;
            int n4 = 8 * g4 + n8;
            int xr = X0 - 48 + 4 * n4;
            bool v = (n4 < 28) && (xr >= 0);
            const float* p = Rbh + (size_t)(2 * (kc * 16 + kp)) * PLANE + (v ? xr : 0);
            ba[s % 3] = v ? *(const float4*)p           : zero4();
            bb[s % 3] = v ? *(const float4*)(p + PLANE) : zero4();
        };
        auto cvB = [&](int s){
            int kc = s >> 2, g4 = s & 3;
            int n4 = 8 * g4 + n8;
            if (n4 < 28){
                uint32_t c16 = (uint32_t)(4 * kc + pw);
                float4 va4 = ba[s % 3], vb4 = bb[s % 3];
                const float va[4] = {va4.x, va4.y, va4.z, va4.w};
                const float vb[4] = {vb4.x, vb4.y, vb4.z, vb4.w};
                #pragma unroll
                for (int e = 0; e < 4; e++){
                    uint32_t n = (uint32_t)(4*n4 + e);
                    uint32_t off = n * ROWB + ((c16 ^ gfun(n)) << 4) + w4;
                    *(uint32_t*)(smem + BF + off) = cvt_f16x2(va[e], vb[e]);
                }
            }
        };

        ldB(0); ldB(1);
        #pragma unroll
        for (int s = 0; s < 16; s++){
            if (s + 2 < 16) ldB(s + 2);
            cvB(s);
            if ((s & 3) == 3) BAR_ARRIVE((s >> 2) + 1, 256);  // slice s>>2 ready
        }
    }

    __syncthreads();                     // Ob complete (consumers), all joined

    // coalesced store: 48 rows x 64 floats
    float* ob = out + (((size_t)b * MAXD) * HH + h) * WW + X0;
    #pragma unroll
    for (int q = tid; q < MAXD * 16; q += 256){
        int i = q >> 4, c4 = q & 15;
        float4 v = *(const float4*)(Ob + i * 68 + 4 * c4);
        *(float4*)(ob + (size_t)i * PLANE + 4 * c4) = v;
    }
}

extern "C" void kernel_launch(void* const* d_in, const int* in_sizes, int n_in,
                              void* d_out, int out_size)
{
    const float* L = (const float*)d_in[0];
    const float* R = (const float*)d_in[1];
    float* out = (float*)d_out;

    cudaFuncSetAttribute(costvol_v13_kernel,
                         cudaFuncAttributeMaxDynamicSharedMemorySize, SMEM_TOTAL);
    dim3 grid(BB * HH * 5);   // 3840 CTAs: (b, h, x-tile of 64)
    costvol_v13_kernel<<<grid, 256, SMEM_TOTAL>>>(L, R, out);
}